// round 1
// baseline (speedup 1.0000x reference)
#include <cuda_runtime.h>

// LSTM_54966991454470: 2-layer LSTM (H=50), T=65536 sequential steps with
// scalar feedback error -> strictly serial recurrence. Persistent single-CTA
// kernel: weights live in registers (packed f32x2 pairs), h/c/gates staged
// through shared memory, packed fma.rn.f32x2 for 2 MACs/lane/instr.

#define T_MAX   65536
#define HDIM    50
#define G4      200      // 4*H gate rows per layer
#define INP     8
#define NTHREADS 224
#define CHUNK   1024     // input prefetch chunk (steps)

typedef unsigned long long u64;

__device__ __forceinline__ u64 pk2(float lo, float hi) {
    u64 r; asm("mov.b64 %0, {%1,%2};" : "=l"(r) : "f"(lo), "f"(hi)); return r;
}
__device__ __forceinline__ float2 upk2(u64 v) {
    float2 f; asm("mov.b64 {%0,%1}, %2;" : "=f"(f.x), "=f"(f.y) : "l"(v)); return f;
}
__device__ __forceinline__ u64 ffma2(u64 a, u64 b, u64 c) {
    u64 d; asm("fma.rn.f32x2 %0, %1, %2, %3;" : "=l"(d) : "l"(a), "l"(b), "l"(c)); return d;
}

__device__ __forceinline__ float sigf(float x) {
    return __fdividef(1.0f, 1.0f + __expf(-x));
}
__device__ __forceinline__ float tanh_fast(float x) {
    // tanh(x) = (1 - e) / (1 + e), e = exp(-2x); clamp to stay finite
    float z = fminf(fmaxf(2.0f * x, -80.0f), 80.0f);
    float e = __expf(-z);
    return __fdividef(1.0f - e, 1.0f + e);
}

__global__ __launch_bounds__(NTHREADS, 1)
void lstm_persist_kernel(const float* __restrict__ input_seq,
                         const float* __restrict__ W_ih1, const float* __restrict__ W_hh1,
                         const float* __restrict__ b_ih1, const float* __restrict__ b_hh1,
                         const float* __restrict__ W_ih2, const float* __restrict__ W_hh2,
                         const float* __restrict__ b_ih2, const float* __restrict__ b_hh2,
                         const float* __restrict__ W_out, const float* __restrict__ b_out,
                         float* __restrict__ out, int T)
{
    __shared__ __align__(16) float sh1[HDIM + 2];       // h1 state
    __shared__ __align__(16) float sh2[HDIM + 2];       // h2 state
    __shared__ __align__(16) float sg[G4];              // gate scratch (both layers)
    __shared__ __align__(16) float swout[HDIM + 2];     // W_out broadcast
    __shared__ __align__(16) float xbuf[CHUNK * INP];   // input staging

    const int t = threadIdx.x;
    const bool is_gate = (t < G4);
    const bool is_unit = (t < HDIM);

    // ---- one-time: pull this thread's weight rows into registers (f32x2 packed)
    u64 wi1[4], wh1[25], wi2[25], wh2[25];
    float bb1 = 0.0f, bb2 = 0.0f;
    if (is_gate) {
        const float* r1 = W_ih1 + t * INP;
        #pragma unroll
        for (int j = 0; j < 4; ++j)  wi1[j] = pk2(r1[2*j], r1[2*j+1]);
        const float* r2 = W_hh1 + t * HDIM;
        #pragma unroll
        for (int j = 0; j < 25; ++j) wh1[j] = pk2(r2[2*j], r2[2*j+1]);
        const float* r3 = W_ih2 + t * HDIM;
        #pragma unroll
        for (int j = 0; j < 25; ++j) wi2[j] = pk2(r3[2*j], r3[2*j+1]);
        const float* r4 = W_hh2 + t * HDIM;
        #pragma unroll
        for (int j = 0; j < 25; ++j) wh2[j] = pk2(r4[2*j], r4[2*j+1]);
        bb1 = b_ih1[t] + b_hh1[t];
        bb2 = b_ih2[t] + b_hh2[t];
    }
    const float bo = b_out[0];
    if (t < HDIM + 2) {
        swout[t] = (t < HDIM) ? W_out[t] : 0.0f;
        sh1[t] = 0.0f;
        sh2[t] = 0.0f;
    }

    float c1 = 0.0f, c2 = 0.0f, err = 0.0f;
    __syncthreads();

    #pragma unroll 1
    for (int step = 0; step < T; ++step) {
        const int lo = step & (CHUNK - 1);
        if (lo == 0) {
            __syncthreads();  // previous chunk's readers done
            const float4* src = (const float4*)(input_seq + (size_t)step * INP);
            float4* dst = (float4*)xbuf;
            int n4 = CHUNK * INP / 4;
            int rem4 = (T - step) * INP / 4;
            if (rem4 < n4) n4 = rem4;
            for (int i = t; i < n4; i += NTHREADS) dst[i] = src[i];
            __syncthreads();
        }
        const float* x = &xbuf[lo * INP];
        const float x7 = x[7];  // act_dist, needed by all threads for err update

        // ---- S1: layer-1 gates: b1 + W_ih1 @ [x0..x6, err] + W_hh1 @ h1
        if (is_gate) {
            float4 xa = *(const float4*)(x);
            float4 xb = *(const float4*)(x + 4);
            u64 a0 = ffma2(wi1[0], pk2(xa.x, xa.y), pk2(bb1, 0.0f));
            u64 a1 = ffma2(wi1[1], pk2(xa.z, xa.w), pk2(0.0f, 0.0f));
            a0 = ffma2(wi1[2], pk2(xb.x, xb.y), a0);
            a1 = ffma2(wi1[3], pk2(xb.z, err), a1);   // W[7] * feedback err
            const u64* hp = (const u64*)sh1;
            #pragma unroll
            for (int j = 0; j < 24; j += 2) {
                a0 = ffma2(wh1[j],     hp[j],     a0);
                a1 = ffma2(wh1[j + 1], hp[j + 1], a1);
            }
            a0 = ffma2(wh1[24], hp[24], a0);
            float2 f0 = upk2(a0), f1 = upk2(a1);
            sg[t] = (f0.x + f1.x) + (f0.y + f1.y);
        }
        __syncthreads();

        // ---- S2: cell 1 update (50 threads)
        if (is_unit) {
            float gi = sigf(sg[t]);
            float gf = sigf(sg[t + HDIM]);
            float gg = tanh_fast(sg[t + 2 * HDIM]);
            float go = sigf(sg[t + 3 * HDIM]);
            c1 = gf * c1 + gi * gg;
            sh1[t] = go * tanh_fast(c1);
        }
        __syncthreads();

        // ---- S3: layer-2 gates: b2 + W_ih2 @ h1 + W_hh2 @ h2
        if (is_gate) {
            const u64* h1p = (const u64*)sh1;
            const u64* h2p = (const u64*)sh2;
            u64 a0 = pk2(bb2, 0.0f), a1 = pk2(0.0f, 0.0f);
            u64 a2 = pk2(0.0f, 0.0f), a3 = pk2(0.0f, 0.0f);
            #pragma unroll
            for (int j = 0; j < 24; j += 2) {
                a0 = ffma2(wi2[j],     h1p[j],     a0);
                a1 = ffma2(wi2[j + 1], h1p[j + 1], a1);
                a2 = ffma2(wh2[j],     h2p[j],     a2);
                a3 = ffma2(wh2[j + 1], h2p[j + 1], a3);
            }
            a0 = ffma2(wi2[24], h1p[24], a0);
            a2 = ffma2(wh2[24], h2p[24], a2);
            float2 f0 = upk2(a0), f1 = upk2(a1), f2 = upk2(a2), f3 = upk2(a3);
            sg[t] = ((f0.x + f1.x) + (f0.y + f1.y)) + ((f2.x + f3.x) + (f2.y + f3.y));
        }
        __syncthreads();

        // ---- S4: cell 2 update (50 threads)
        if (is_unit) {
            float gi = sigf(sg[t]);
            float gf = sigf(sg[t + HDIM]);
            float gg = tanh_fast(sg[t + 2 * HDIM]);
            float go = sigf(sg[t + 3 * HDIM]);
            c2 = gf * c2 + gi * gg;
            sh2[t] = go * tanh_fast(c2);
        }
        __syncthreads();

        // ---- S5: output + feedback error. Computed redundantly in EVERY
        // thread so err lands in-register everywhere (no broadcast barrier).
        {
            const u64* h2p = (const u64*)sh2;
            const u64* wop = (const u64*)swout;
            u64 a0 = pk2(0.0f, 0.0f), a1 = pk2(0.0f, 0.0f);
            #pragma unroll
            for (int j = 0; j < 24; j += 2) {
                a0 = ffma2(wop[j],     h2p[j],     a0);
                a1 = ffma2(wop[j + 1], h2p[j + 1], a1);
            }
            a0 = ffma2(wop[24], h2p[24], a0);
            float2 f0 = upk2(a0), f1 = upk2(a1);
            float y = bo + (f0.x + f1.x) + (f0.y + f1.y);
            err = 0.9f * err + 0.1f * (x7 - y);
            if (t == 0) out[step] = y;
        }
        // No trailing barrier needed: next S1 only writes sg (no S5 reader)
        // and reads sh1/xbuf which are barrier-protected upstream.
    }
}

extern "C" void kernel_launch(void* const* d_in, const int* in_sizes, int n_in,
                              void* d_out, int out_size) {
    const int T = in_sizes[0] / INP;
    lstm_persist_kernel<<<1, NTHREADS>>>(
        (const float*)d_in[0],
        (const float*)d_in[1], (const float*)d_in[2],
        (const float*)d_in[3], (const float*)d_in[4],
        (const float*)d_in[5], (const float*)d_in[6],
        (const float*)d_in[7], (const float*)d_in[8],
        (const float*)d_in[9], (const float*)d_in[10],
        (float*)d_out, T);
}